// round 14
// baseline (speedup 1.0000x reference)
#include <cuda_runtime.h>
#include <cuda_bf16.h>
#include <math_constants.h>

#define EPSF 1e-7f
#define NMAX 8192
#define L2E  1.44269504f

// Interleaved per-box features: 3 float4 per box (single base pointer in loop).
//  [3i+0] = x1, y1, x2, y2
//  [3i+1] = area, 0.5*(x1+x2), 0.5*(y1+y2), (2/pi)*atan(w/(h+eps))
//  [3i+2] = conf, w, h, (spare)
__device__ float4 g_F[NMAX * 3];

__global__ void tgam_prep(const float* __restrict__ x, int n) {
    int i = blockIdx.x * blockDim.x + threadIdx.x;
    if (i >= n) return;
    float conf = x[i * 5 + 0];
    float x1 = x[i * 5 + 1];
    float y1 = x[i * 5 + 2];
    float x2 = x[i * 5 + 3];
    float y2 = x[i * 5 + 4];
    float w = x2 - x1;
    float h = y2 - y1;
    const float TWO_OVER_PI = 0.63661977236758134f;
    g_F[3 * i + 0] = make_float4(x1, y1, x2, y2);
    g_F[3 * i + 1] = make_float4(w * h, 0.5f * (x1 + x2), 0.5f * (y1 + y2),
                                 TWO_OVER_PI * atanf(__fdividef(w, h + EPSF)));
    g_F[3 * i + 2] = make_float4(conf, w, h, 0.0f);
}

__device__ __forceinline__ float safe_sigmoid(float xp) {
    float r = __fdividef(1.0f, 1.0f + __expf(-xp));
    return isfinite(r) ? r : 0.5f;
}

__device__ __forceinline__ float rcpf(float x) {
    float r; asm("rcp.approx.f32 %0, %1;" : "=f"(r) : "f"(x)); return r;
}
__device__ __forceinline__ float ex2f(float x) {
    float r; asm("ex2.approx.f32 %0, %1;" : "=f"(r) : "f"(x)); return r;
}

struct RowFeat {
    float x1, y1, x2, y2;   // box
    float biE;              // area + EPSF
    float sxh, syh;         // half center sums
    float atK;              // (2/pi)*atan
    float w, h;             // width, height
    float cil2;             // conf * log2(e)
    float conf;
};

__device__ __forceinline__ RowFeat load_row(int i) {
    RowFeat r;
    float4 A = g_F[3 * i + 0];
    float4 B = g_F[3 * i + 1];
    float4 C = g_F[3 * i + 2];
    r.x1 = A.x; r.y1 = A.y; r.x2 = A.z; r.y2 = A.w;
    r.biE = B.x + EPSF;
    r.sxh = B.y; r.syh = B.z; r.atK = B.w;
    r.conf = C.x; r.w = C.y; r.h = C.z;
    r.cil2 = C.x * L2E;
    return r;
}

// Per-pair score. Exact CIoU math with per-box constants prefolded:
//  - cw = (wi+wj) - iw_raw       (min+max identity)
//  - v  = da^2, da in (2/pi)*atan units (K prefolded)
//  - rho2 = dx^2+dy^2 with half center sums (0.25 prefolded)
//  - v*alpha = v^2/den           (one fused divide)
//  - p = ex2(ciou * cil2 * cj)   (log2e prefolded)
//  - iou clamped to 1: NaN-proof (den >= EPSF) + closer to IEEE divide
__device__ __forceinline__ float score(
    const RowFeat& Ri, const float4 Fa, const float4 Fb, const float4 Fc)
{
    float iwr = fminf(Ri.x2, Fa.z) - fmaxf(Ri.x1, Fa.x);
    float ihr = fminf(Ri.y2, Fa.w) - fmaxf(Ri.y1, Fa.y);
    float inter = fmaxf(iwr, 0.0f) * fmaxf(ihr, 0.0f);

    float uni = (Ri.biE + Fb.x) - inter;
    float iou = fminf(inter * rcpf(uni), 1.0f);

    float cw = (Ri.w + Fc.y) - iwr;
    float ch = (Ri.h + Fc.z) - ihr;
    float c2 = fmaf(cw, cw, fmaf(ch, ch, EPSF));

    float dx = Fb.y - Ri.sxh;
    float dy = Fb.z - Ri.syh;
    float rho2 = fmaf(dx, dx, dy * dy);

    float da = Fb.w - Ri.atK;
    float v  = da * da;
    float den = (v + (1.0f + EPSF)) - iou;   // >= EPSF since iou <= 1

    float t23 = fmaf(rho2, rcpf(c2), (v * v) * rcpf(den));
    float ciou = iou - t23;

    return ex2f(ciou * (Ri.cil2 * Fc.x));
}

#define BT 128   // threads per CTA

// Two rows per CTA, 128 threads: 32 loop iterations/warp (2x amortization of
// prologue + reduction vs 256t), half the total warps. Handles any n (tail
// row duplicated, write guarded).
__global__ __launch_bounds__(BT) void tgam_attn2(
    const float* __restrict__ gamma_p, float* __restrict__ out, int n)
{
    const int i0 = blockIdx.x * 2;
    const int i1 = (i0 + 1 < n) ? (i0 + 1) : i0;
    const int tid = threadIdx.x;

    const RowFeat R0 = load_row(i0);
    const RowFeat R1 = load_row(i1);

    float l0 = 0.f, b00 = 0.f, b01 = 0.f, b02 = 0.f, b03 = 0.f, b04 = 0.f;
    float l1 = 0.f, b10 = 0.f, b11 = 0.f, b12 = 0.f, b13 = 0.f, b14 = 0.f;

    // Byte-stride pointer walk: one IADD per step instead of per-load IMAD.
    const char* __restrict__ fp = (const char*)(g_F + 3 * tid);
    const int iters = (n - 1 - tid) / BT + ((tid < n) ? 1 : 0);

#pragma unroll 4
    for (int it = 0; it < iters; it++, fp += BT * 3 * sizeof(float4)) {
        const float4 Fa = ((const float4*)fp)[0];
        const float4 Fb = ((const float4*)fp)[1];
        const float4 Fc = ((const float4*)fp)[2];

        const float p0 = score(R0, Fa, Fb, Fc);
        l0  += p0;
        b00 += p0 * Fc.x;
        b01 += p0 * Fa.x;
        b02 += p0 * Fa.y;
        b03 += p0 * Fa.z;
        b04 += p0 * Fa.w;

        const float p1 = score(R1, Fa, Fb, Fc);
        l1  += p1;
        b10 += p1 * Fc.x;
        b11 += p1 * Fa.x;
        b12 += p1 * Fa.y;
        b13 += p1 * Fa.z;
        b14 += p1 * Fa.w;
    }

    // ---- block reduction of 12 values (4 warps) ----
#pragma unroll
    for (int o = 16; o > 0; o >>= 1) {
        l0  += __shfl_xor_sync(0xFFFFFFFFu, l0,  o);
        b00 += __shfl_xor_sync(0xFFFFFFFFu, b00, o);
        b01 += __shfl_xor_sync(0xFFFFFFFFu, b01, o);
        b02 += __shfl_xor_sync(0xFFFFFFFFu, b02, o);
        b03 += __shfl_xor_sync(0xFFFFFFFFu, b03, o);
        b04 += __shfl_xor_sync(0xFFFFFFFFu, b04, o);
        l1  += __shfl_xor_sync(0xFFFFFFFFu, l1,  o);
        b10 += __shfl_xor_sync(0xFFFFFFFFu, b10, o);
        b11 += __shfl_xor_sync(0xFFFFFFFFu, b11, o);
        b12 += __shfl_xor_sync(0xFFFFFFFFu, b12, o);
        b13 += __shfl_xor_sync(0xFFFFFFFFu, b13, o);
        b14 += __shfl_xor_sync(0xFFFFFFFFu, b14, o);
    }

    __shared__ float red[4][12];
    const int warp = tid >> 5;
    const int lane = tid & 31;
    if (lane == 0) {
        red[warp][0]  = l0;  red[warp][1]  = b00; red[warp][2]  = b01;
        red[warp][3]  = b02; red[warp][4]  = b03; red[warp][5]  = b04;
        red[warp][6]  = l1;  red[warp][7]  = b10; red[warp][8]  = b11;
        red[warp][9]  = b12; red[warp][10] = b13; red[warp][11] = b14;
    }
    __syncthreads();

    if (tid == 0) {
        float S[12];
#pragma unroll
        for (int v = 0; v < 12; v++)
            S[v] = red[0][v] + red[1][v] + red[2][v] + red[3][v];

        float g = gamma_p[0];
        if (!isfinite(g)) g = 0.0f;

        {
            const float inv = __fdividef(1.0f, S[0]);
            out[i0 * 5 + 0] = safe_sigmoid(R0.conf * g + S[1] * inv);
            out[i0 * 5 + 1] = safe_sigmoid(R0.x1   * g + S[2] * inv);
            out[i0 * 5 + 2] = safe_sigmoid(R0.y1   * g + S[3] * inv);
            out[i0 * 5 + 3] = safe_sigmoid(R0.x2   * g + S[4] * inv);
            out[i0 * 5 + 4] = safe_sigmoid(R0.y2   * g + S[5] * inv);
        }
        if (i1 != i0) {
            const float inv = __fdividef(1.0f, S[6]);
            out[i1 * 5 + 0] = safe_sigmoid(R1.conf * g + S[7]  * inv);
            out[i1 * 5 + 1] = safe_sigmoid(R1.x1   * g + S[8]  * inv);
            out[i1 * 5 + 2] = safe_sigmoid(R1.y1   * g + S[9]  * inv);
            out[i1 * 5 + 3] = safe_sigmoid(R1.x2   * g + S[10] * inv);
            out[i1 * 5 + 4] = safe_sigmoid(R1.y2   * g + S[11] * inv);
        }
    }
}

extern "C" void kernel_launch(void* const* d_in, const int* in_sizes, int n_in,
                              void* d_out, int out_size) {
    // x = the big tensor, gamma = the 1-element one (ordering-proof).
    int xi = 0, gi = (n_in > 1) ? 1 : 0;
    if (n_in > 1 && in_sizes[1] > in_sizes[0]) { xi = 1; gi = 0; }

    const float* x     = (const float*)d_in[xi];
    const float* gamma = (const float*)d_in[gi];
    float* out         = (float*)d_out;

    // Bytes-vs-elements detection via the 1-element gamma.
    const int denom = (n_in > 1 && in_sizes[gi] == 4) ? 20 : 5;
    int n = in_sizes[xi] / denom;
    if (out_size > 0) {
        int n_out = out_size / denom;
        if (n_out > 0 && n_out < n) n = n_out;
    }
    if (n > NMAX) n = NMAX;
    if (n <= 0) n = 1;

    tgam_prep<<<(n + 127) / 128, 128>>>(x, n);
    tgam_attn2<<<(n + 1) / 2, BT>>>(gamma, out, n);
}

// round 15
// speedup vs baseline: 1.0314x; 1.0314x over previous
#include <cuda_runtime.h>
#include <cuda_bf16.h>
#include <math_constants.h>

#define EPSF 1e-7f
#define NMAX 8192
#define L2E  1.44269504f

// Interleaved per-box features: 3 float4 per box (single base pointer in loop).
//  [3i+0] = x1, y1, x2, y2
//  [3i+1] = area, 0.5*(x1+x2), 0.5*(y1+y2), (2/pi)*atan(w/(h+eps))
//  [3i+2] = conf, w, h, (spare)
__device__ float4 g_F[NMAX * 3];

__global__ void tgam_prep(const float* __restrict__ x, int n) {
    int i = blockIdx.x * blockDim.x + threadIdx.x;
    if (i >= n) return;
    float conf = x[i * 5 + 0];
    float x1 = x[i * 5 + 1];
    float y1 = x[i * 5 + 2];
    float x2 = x[i * 5 + 3];
    float y2 = x[i * 5 + 4];
    float w = x2 - x1;
    float h = y2 - y1;
    const float TWO_OVER_PI = 0.63661977236758134f;
    g_F[3 * i + 0] = make_float4(x1, y1, x2, y2);
    g_F[3 * i + 1] = make_float4(w * h, 0.5f * (x1 + x2), 0.5f * (y1 + y2),
                                 TWO_OVER_PI * atanf(__fdividef(w, h + EPSF)));
    g_F[3 * i + 2] = make_float4(conf, w, h, 0.0f);
}

__device__ __forceinline__ float safe_sigmoid(float xp) {
    float r = __fdividef(1.0f, 1.0f + __expf(-xp));
    return isfinite(r) ? r : 0.5f;
}

__device__ __forceinline__ float rcpf(float x) {
    float r; asm("rcp.approx.f32 %0, %1;" : "=f"(r) : "f"(x)); return r;
}
__device__ __forceinline__ float ex2f(float x) {
    float r; asm("ex2.approx.f32 %0, %1;" : "=f"(r) : "f"(x)); return r;
}

struct RowFeat {
    float x1, y1, x2, y2;   // box
    float biE;              // area + EPSF
    float sxh, syh;         // half center sums
    float atK;              // (2/pi)*atan
    float w, h;             // width, height
    float cil2;             // conf * log2(e)
    float conf;
};

__device__ __forceinline__ RowFeat load_row(int i) {
    RowFeat r;
    float4 A = g_F[3 * i + 0];
    float4 B = g_F[3 * i + 1];
    float4 C = g_F[3 * i + 2];
    r.x1 = A.x; r.y1 = A.y; r.x2 = A.z; r.y2 = A.w;
    r.biE = B.x + EPSF;
    r.sxh = B.y; r.syh = B.z; r.atK = B.w;
    r.conf = C.x; r.w = C.y; r.h = C.z;
    r.cil2 = C.x * L2E;
    return r;
}

// Per-pair score. Exact CIoU math with per-box constants prefolded:
//  - cw = (wi+wj) - iw_raw   (min+max identity)
//  - v  = da^2 with da in (2/pi)*atan units (K prefolded)
//  - rho2 = dx^2+dy^2 with half center sums (0.25 prefolded)
//  - rho2/c2 + v*alpha as one FMA over two rcp's (combined-divide epilogue)
//  - p = ex2(ciou * cil2 * cj) (log2e prefolded)
//  - iou clamped to 1: NaN-proof (den >= EPSF) + closer to IEEE divide
__device__ __forceinline__ float score(
    const RowFeat& Ri, const float4 Fa, const float4 Fb, const float4 Fc)
{
    float iwr = fminf(Ri.x2, Fa.z) - fmaxf(Ri.x1, Fa.x);
    float ihr = fminf(Ri.y2, Fa.w) - fmaxf(Ri.y1, Fa.y);
    float iw = fmaxf(iwr, 0.0f);
    float ih = fmaxf(ihr, 0.0f);
    float inter = iw * ih;

    float uni = (Ri.biE + Fb.x) - inter;
    float iou = fminf(__fdividef(inter, uni), 1.0f);

    float cw = (Ri.w + Fc.y) - iwr;
    float ch = (Ri.h + Fc.z) - ihr;
    float c2 = fmaf(cw, cw, fmaf(ch, ch, EPSF));

    float dx = Fb.y - Ri.sxh;
    float dy = Fb.z - Ri.syh;
    float rho2 = fmaf(dx, dx, dy * dy);

    float da = Fb.w - Ri.atK;
    float v  = da * da;
    float den = (v + (1.0f + EPSF)) - iou;   // >= EPSF since iou <= 1

    // combined-divide: rho2/c2 + v^2/den in one FMA (saves 1 issue vs R9)
    float t23 = fmaf(rho2, rcpf(c2), (v * v) * rcpf(den));
    float ciou = iou - t23;

    float s2 = ciou * (Ri.cil2 * Fc.x);
    return ex2f(s2);
}

// Two rows per CTA, 256 threads (the R9 proven configuration).
__global__ __launch_bounds__(256) void tgam_attn2(
    const float* __restrict__ gamma_p, float* __restrict__ out, int n)
{
    const int i0 = blockIdx.x * 2;
    const int i1 = (i0 + 1 < n) ? (i0 + 1) : i0;
    const int tid = threadIdx.x;

    const RowFeat R0 = load_row(i0);
    const RowFeat R1 = load_row(i1);

    float l0 = 0.f, b00 = 0.f, b01 = 0.f, b02 = 0.f, b03 = 0.f, b04 = 0.f;
    float l1 = 0.f, b10 = 0.f, b11 = 0.f, b12 = 0.f, b13 = 0.f, b14 = 0.f;

#pragma unroll 4
    for (int j = tid; j < n; j += 256) {
        const float4 Fa = g_F[3 * j + 0];
        const float4 Fb = g_F[3 * j + 1];
        const float4 Fc = g_F[3 * j + 2];

        const float p0 = score(R0, Fa, Fb, Fc);
        l0  += p0;
        b00 += p0 * Fc.x;
        b01 += p0 * Fa.x;
        b02 += p0 * Fa.y;
        b03 += p0 * Fa.z;
        b04 += p0 * Fa.w;

        const float p1 = score(R1, Fa, Fb, Fc);
        l1  += p1;
        b10 += p1 * Fc.x;
        b11 += p1 * Fa.x;
        b12 += p1 * Fa.y;
        b13 += p1 * Fa.z;
        b14 += p1 * Fa.w;
    }

    // ---- block reduction of 12 values ----
#pragma unroll
    for (int o = 16; o > 0; o >>= 1) {
        l0  += __shfl_xor_sync(0xFFFFFFFFu, l0,  o);
        b00 += __shfl_xor_sync(0xFFFFFFFFu, b00, o);
        b01 += __shfl_xor_sync(0xFFFFFFFFu, b01, o);
        b02 += __shfl_xor_sync(0xFFFFFFFFu, b02, o);
        b03 += __shfl_xor_sync(0xFFFFFFFFu, b03, o);
        b04 += __shfl_xor_sync(0xFFFFFFFFu, b04, o);
        l1  += __shfl_xor_sync(0xFFFFFFFFu, l1,  o);
        b10 += __shfl_xor_sync(0xFFFFFFFFu, b10, o);
        b11 += __shfl_xor_sync(0xFFFFFFFFu, b11, o);
        b12 += __shfl_xor_sync(0xFFFFFFFFu, b12, o);
        b13 += __shfl_xor_sync(0xFFFFFFFFu, b13, o);
        b14 += __shfl_xor_sync(0xFFFFFFFFu, b14, o);
    }

    __shared__ float red[8][12];
    const int warp = tid >> 5;
    const int lane = tid & 31;
    if (lane == 0) {
        red[warp][0]  = l0;  red[warp][1]  = b00; red[warp][2]  = b01;
        red[warp][3]  = b02; red[warp][4]  = b03; red[warp][5]  = b04;
        red[warp][6]  = l1;  red[warp][7]  = b10; red[warp][8]  = b11;
        red[warp][9]  = b12; red[warp][10] = b13; red[warp][11] = b14;
    }
    __syncthreads();

    if (tid == 0) {
        float S[12];
#pragma unroll
        for (int v = 0; v < 12; v++) {
            float s = 0.f;
#pragma unroll
            for (int w = 0; w < 8; w++) s += red[w][v];
            S[v] = s;
        }
        float g = gamma_p[0];
        if (!isfinite(g)) g = 0.0f;

        {
            const float inv = __fdividef(1.0f, S[0]);
            out[i0 * 5 + 0] = safe_sigmoid(R0.conf * g + S[1] * inv);
            out[i0 * 5 + 1] = safe_sigmoid(R0.x1   * g + S[2] * inv);
            out[i0 * 5 + 2] = safe_sigmoid(R0.y1   * g + S[3] * inv);
            out[i0 * 5 + 3] = safe_sigmoid(R0.x2   * g + S[4] * inv);
            out[i0 * 5 + 4] = safe_sigmoid(R0.y2   * g + S[5] * inv);
        }
        if (i1 != i0) {
            const float inv = __fdividef(1.0f, S[6]);
            out[i1 * 5 + 0] = safe_sigmoid(R1.conf * g + S[7]  * inv);
            out[i1 * 5 + 1] = safe_sigmoid(R1.x1   * g + S[8]  * inv);
            out[i1 * 5 + 2] = safe_sigmoid(R1.y1   * g + S[9]  * inv);
            out[i1 * 5 + 3] = safe_sigmoid(R1.x2   * g + S[10] * inv);
            out[i1 * 5 + 4] = safe_sigmoid(R1.y2   * g + S[11] * inv);
        }
    }
}

extern "C" void kernel_launch(void* const* d_in, const int* in_sizes, int n_in,
                              void* d_out, int out_size) {
    // x = the big tensor, gamma = the 1-element one (ordering-proof).
    int xi = 0, gi = (n_in > 1) ? 1 : 0;
    if (n_in > 1 && in_sizes[1] > in_sizes[0]) { xi = 1; gi = 0; }

    const float* x     = (const float*)d_in[xi];
    const float* gamma = (const float*)d_in[gi];
    float* out         = (float*)d_out;

    // Bytes-vs-elements detection via the 1-element gamma.
    const int denom = (n_in > 1 && in_sizes[gi] == 4) ? 20 : 5;
    int n = in_sizes[xi] / denom;
    if (out_size > 0) {
        int n_out = out_size / denom;
        if (n_out > 0 && n_out < n) n = n_out;
    }
    if (n > NMAX) n = NMAX;
    if (n <= 0) n = 1;

    // Prep is latency-bound: spread it over more CTAs (block 64).
    tgam_prep<<<(n + 63) / 64, 64>>>(x, n);
    tgam_attn2<<<(n + 1) / 2, 256>>>(gamma, out, n);
}

// round 16
// speedup vs baseline: 1.1069x; 1.0732x over previous
#include <cuda_runtime.h>
#include <cuda_bf16.h>
#include <math_constants.h>

#define EPSF 1e-7f
#define NMAX 8192
#define L2E  1.44269504f

// Interleaved per-box features: 3 float4 per box (single base pointer in loop).
//  [3i+0] = x1, y1, x2, y2
//  [3i+1] = area, 0.5*(x1+x2), 0.5*(y1+y2), (2/pi)*atan(w/(h+eps))
//  [3i+2] = conf, w, h, (spare)
__device__ float4 g_F[NMAX * 3];

__global__ void tgam_prep(const float* __restrict__ x, int n) {
    int i = blockIdx.x * blockDim.x + threadIdx.x;
    if (i >= n) return;
    float conf = x[i * 5 + 0];
    float x1 = x[i * 5 + 1];
    float y1 = x[i * 5 + 2];
    float x2 = x[i * 5 + 3];
    float y2 = x[i * 5 + 4];
    float w = x2 - x1;
    float h = y2 - y1;
    const float TWO_OVER_PI = 0.63661977236758134f;
    g_F[3 * i + 0] = make_float4(x1, y1, x2, y2);
    g_F[3 * i + 1] = make_float4(w * h, 0.5f * (x1 + x2), 0.5f * (y1 + y2),
                                 TWO_OVER_PI * atanf(__fdividef(w, h + EPSF)));
    g_F[3 * i + 2] = make_float4(conf, w, h, 0.0f);
}

__device__ __forceinline__ float safe_sigmoid(float xp) {
    float r = __fdividef(1.0f, 1.0f + __expf(-xp));
    return isfinite(r) ? r : 0.5f;
}

struct RowFeat {
    float x1, y1, x2, y2;   // box
    float biE;              // area + EPSF
    float sxh, syh;         // half center sums
    float atK;              // (2/pi)*atan
    float w, h;             // width, height
    float cil2;             // conf * log2(e)
    float conf;
};

__device__ __forceinline__ RowFeat load_row(int i) {
    RowFeat r;
    float4 A = g_F[3 * i + 0];
    float4 B = g_F[3 * i + 1];
    float4 C = g_F[3 * i + 2];
    r.x1 = A.x; r.y1 = A.y; r.x2 = A.z; r.y2 = A.w;
    r.biE = B.x + EPSF;
    r.sxh = B.y; r.syh = B.z; r.atK = B.w;
    r.conf = C.x; r.w = C.y; r.h = C.z;
    r.cil2 = C.x * L2E;
    return r;
}

// Per-pair score — EXACT R9 code (the measured-fastest variant):
// intrinsic __fdividef for all three divides (NVVM-visible, no asm MOV tax),
// single trailing ex2 asm. Per-box constants prefolded (K, 0.25, log2e);
// cw via min+max identity; iou clamped to 1 (NaN-proof: den >= EPSF).
__device__ __forceinline__ float score(
    const RowFeat& Ri, const float4 Fa, const float4 Fb, const float4 Fc)
{
    float iwr = fminf(Ri.x2, Fa.z) - fmaxf(Ri.x1, Fa.x);
    float ihr = fminf(Ri.y2, Fa.w) - fmaxf(Ri.y1, Fa.y);
    float iw = fmaxf(iwr, 0.0f);
    float ih = fmaxf(ihr, 0.0f);
    float inter = iw * ih;

    float uni = (Ri.biE + Fb.x) - inter;
    float iou = fminf(__fdividef(inter, uni), 1.0f);

    float cw = (Ri.w + Fc.y) - iwr;
    float ch = (Ri.h + Fc.z) - ihr;
    float c2 = fmaf(cw, cw, fmaf(ch, ch, EPSF));

    float dx = Fb.y - Ri.sxh;
    float dy = Fb.z - Ri.syh;
    float rho2 = fmaf(dx, dx, dy * dy);
    float t2 = __fdividef(rho2, c2);

    float da = Fb.w - Ri.atK;
    float v  = da * da;
    float den = (v + (1.0f + EPSF)) - iou;  // >= EPSF since iou <= 1
    float t3 = __fdividef(v * v, den);      // = v * alpha

    float ciou = (iou - t2) - t3;

    float s2 = ciou * (Ri.cil2 * Fc.x);
    float p;
    asm("ex2.approx.f32 %0, %1;" : "=f"(p) : "f"(s2));
    return p;
}

// Two rows per CTA, 256 threads — EXACT R9 configuration.
__global__ __launch_bounds__(256) void tgam_attn2(
    const float* __restrict__ gamma_p, float* __restrict__ out, int n)
{
    const int i0 = blockIdx.x * 2;
    const int i1 = (i0 + 1 < n) ? (i0 + 1) : i0;
    const int tid = threadIdx.x;

    const RowFeat R0 = load_row(i0);
    const RowFeat R1 = load_row(i1);

    float l0 = 0.f, b00 = 0.f, b01 = 0.f, b02 = 0.f, b03 = 0.f, b04 = 0.f;
    float l1 = 0.f, b10 = 0.f, b11 = 0.f, b12 = 0.f, b13 = 0.f, b14 = 0.f;

#pragma unroll 4
    for (int j = tid; j < n; j += 256) {
        const float4 Fa = g_F[3 * j + 0];
        const float4 Fb = g_F[3 * j + 1];
        const float4 Fc = g_F[3 * j + 2];

        const float p0 = score(R0, Fa, Fb, Fc);
        l0  += p0;
        b00 += p0 * Fc.x;
        b01 += p0 * Fa.x;
        b02 += p0 * Fa.y;
        b03 += p0 * Fa.z;
        b04 += p0 * Fa.w;

        const float p1 = score(R1, Fa, Fb, Fc);
        l1  += p1;
        b10 += p1 * Fc.x;
        b11 += p1 * Fa.x;
        b12 += p1 * Fa.y;
        b13 += p1 * Fa.z;
        b14 += p1 * Fa.w;
    }

    // ---- block reduction of 12 values ----
#pragma unroll
    for (int o = 16; o > 0; o >>= 1) {
        l0  += __shfl_xor_sync(0xFFFFFFFFu, l0,  o);
        b00 += __shfl_xor_sync(0xFFFFFFFFu, b00, o);
        b01 += __shfl_xor_sync(0xFFFFFFFFu, b01, o);
        b02 += __shfl_xor_sync(0xFFFFFFFFu, b02, o);
        b03 += __shfl_xor_sync(0xFFFFFFFFu, b03, o);
        b04 += __shfl_xor_sync(0xFFFFFFFFu, b04, o);
        l1  += __shfl_xor_sync(0xFFFFFFFFu, l1,  o);
        b10 += __shfl_xor_sync(0xFFFFFFFFu, b10, o);
        b11 += __shfl_xor_sync(0xFFFFFFFFu, b11, o);
        b12 += __shfl_xor_sync(0xFFFFFFFFu, b12, o);
        b13 += __shfl_xor_sync(0xFFFFFFFFu, b13, o);
        b14 += __shfl_xor_sync(0xFFFFFFFFu, b14, o);
    }

    __shared__ float red[8][12];
    const int warp = tid >> 5;
    const int lane = tid & 31;
    if (lane == 0) {
        red[warp][0]  = l0;  red[warp][1]  = b00; red[warp][2]  = b01;
        red[warp][3]  = b02; red[warp][4]  = b03; red[warp][5]  = b04;
        red[warp][6]  = l1;  red[warp][7]  = b10; red[warp][8]  = b11;
        red[warp][9]  = b12; red[warp][10] = b13; red[warp][11] = b14;
    }
    __syncthreads();

    if (tid == 0) {
        float S[12];
#pragma unroll
        for (int v = 0; v < 12; v++) {
            float s = 0.f;
#pragma unroll
            for (int w = 0; w < 8; w++) s += red[w][v];
            S[v] = s;
        }
        float g = gamma_p[0];
        if (!isfinite(g)) g = 0.0f;

        {
            const float inv = __fdividef(1.0f, S[0]);
            out[i0 * 5 + 0] = safe_sigmoid(R0.conf * g + S[1] * inv);
            out[i0 * 5 + 1] = safe_sigmoid(R0.x1   * g + S[2] * inv);
            out[i0 * 5 + 2] = safe_sigmoid(R0.y1   * g + S[3] * inv);
            out[i0 * 5 + 3] = safe_sigmoid(R0.x2   * g + S[4] * inv);
            out[i0 * 5 + 4] = safe_sigmoid(R0.y2   * g + S[5] * inv);
        }
        if (i1 != i0) {
            const float inv = __fdividef(1.0f, S[6]);
            out[i1 * 5 + 0] = safe_sigmoid(R1.conf * g + S[7]  * inv);
            out[i1 * 5 + 1] = safe_sigmoid(R1.x1   * g + S[8]  * inv);
            out[i1 * 5 + 2] = safe_sigmoid(R1.y1   * g + S[9]  * inv);
            out[i1 * 5 + 3] = safe_sigmoid(R1.x2   * g + S[10] * inv);
            out[i1 * 5 + 4] = safe_sigmoid(R1.y2   * g + S[11] * inv);
        }
    }
}

extern "C" void kernel_launch(void* const* d_in, const int* in_sizes, int n_in,
                              void* d_out, int out_size) {
    // x = the big tensor, gamma = the 1-element one (ordering-proof).
    int xi = 0, gi = (n_in > 1) ? 1 : 0;
    if (n_in > 1 && in_sizes[1] > in_sizes[0]) { xi = 1; gi = 0; }

    const float* x     = (const float*)d_in[xi];
    const float* gamma = (const float*)d_in[gi];
    float* out         = (float*)d_out;

    // Bytes-vs-elements detection via the 1-element gamma.
    const int denom = (n_in > 1 && in_sizes[gi] == 4) ? 20 : 5;
    int n = in_sizes[xi] / denom;
    if (out_size > 0) {
        int n_out = out_size / denom;
        if (n_out > 0 && n_out < n) n = n_out;
    }
    if (n > NMAX) n = NMAX;
    if (n <= 0) n = 1;

    // Prep is latency-bound: spread over 64 CTAs.
    tgam_prep<<<(n + 63) / 64, 64>>>(x, n);
    tgam_attn2<<<(n + 1) / 2, 256>>>(gamma, out, n);
}